// round 8
// baseline (speedup 1.0000x reference)
#include <cuda_runtime.h>
#include <math.h>

#define NREG 36
#define EMBD 1024
#define SIMD 16
#define HIDD 32
#define NKER 8

__device__ __forceinline__ void dot3(float& q, float& n, float& x, const float4 a, const float4 c) {
    q = fmaf(a.x, a.x, q); q = fmaf(a.y, a.y, q); q = fmaf(a.z, a.z, q); q = fmaf(a.w, a.w, q);
    n = fmaf(c.x, c.x, n); n = fmaf(c.y, c.y, n); n = fmaf(c.z, c.z, n); n = fmaf(c.w, c.w, n);
    x = fmaf(a.x, c.x, x); x = fmaf(a.y, c.y, x); x = fmaf(a.z, c.z, x); x = fmaf(a.w, c.w, x);
}

// 64-thread CTAs, 18/SM cap -> grid 2048 fits in ONE cooperative wave (148*18=2664).
__global__ void __launch_bounds__(64, 18)
simgsmn_main(const float* __restrict__ inp1, const float* __restrict__ inp2,
             const float* __restrict__ gcn_w, const float* __restrict__ out1_v,
             const float* __restrict__ out1_g, const float* __restrict__ out1_b,
             const float* __restrict__ out2_v, const float* __restrict__ out2_g,
             const float* __restrict__ out2_b, float* __restrict__ out)
{
    __shared__ float sv[NREG * SIMD];
    __shared__ float W1fs[SIMD * HIDD];
    __shared__ float gs[SIMD * HIDD];     // temp: sum_k gcn_w
    __shared__ float w1t[HIDD * HIDD];    // temp: weight-normed out1
    __shared__ float w2ss[HIDD];
    __shared__ float b1s[HIDD];
    __shared__ float red[2];
    __shared__ float b2sh;

    const int tid  = threadIdx.x;
    const int w    = tid >> 5;      // 2 warps
    const int lane = tid & 31;
    const int g    = lane >> 2;     // group owns sim blocks {2g, 2g+1}
    const int c4   = lane & 3;
    const int b    = blockIdx.x;

    // ---- streaming prologue FIRST (loads in flight while constants fold) ----
    const size_t bstride = (size_t)(NREG * EMBD / 4);
    const int loff = w * 256 + g * 32 + c4;   // row w, lane slot
    const float4* p1 = reinterpret_cast<const float4*>(inp1) + (size_t)b * bstride + loff;
    const float4* p2 = reinterpret_cast<const float4*>(inp2) + (size_t)b * bstride + loff;

    float4 A0 = __ldcs(p1 +  0), C0 = __ldcs(p2 +  0);
    float4 A1 = __ldcs(p1 +  4), C1 = __ldcs(p2 +  4);
    float4 A2 = __ldcs(p1 +  8), C2 = __ldcs(p2 +  8);
    float4 A3 = __ldcs(p1 + 12), C3 = __ldcs(p2 + 12);

    // ---- per-CTA constant folding (L2-hot after first CTAs) ----
    for (int i = tid; i < SIMD * HIDD; i += 64) {
        float a = 0.f;
        #pragma unroll
        for (int k = 0; k < NKER; k++) a += gcn_w[k * SIMD * HIDD + i];
        gs[i] = a;
    }
    if (tid < HIDD) {
        float ss = 0.f;
        #pragma unroll
        for (int h = 0; h < HIDD; h++) { float v = out1_v[tid * HIDD + h]; ss += v * v; }
        const float sc = out1_g[tid] / (sqrtf(ss) + 1e-12f);
        #pragma unroll
        for (int h = 0; h < HIDD; h++) w1t[tid * HIDD + h] = out1_v[tid * HIDD + h] * sc;
        b1s[tid] = out1_b[tid];
    }
    if (tid == 32) {
        float ss = 0.f;
        #pragma unroll
        for (int h = 0; h < HIDD; h++) { float v = out2_v[h]; ss += v * v; }
        const float sc = out2_g[0] / (sqrtf(ss) + 1e-12f);
        #pragma unroll
        for (int h = 0; h < HIDD; h++) w2ss[h] = out2_v[h] * sc * (1.0f / 36.0f);
        b2sh = out2_b[0];
    }
    __syncthreads();
    for (int i = tid; i < SIMD * HIDD; i += 64) {
        const int d = i >> 5, hh = i & 31;
        float acc = 0.f;
        #pragma unroll
        for (int h = 0; h < HIDD; h++)
            acc = fmaf(gs[d * HIDD + h], w1t[hh * HIDD + h], acc);
        W1fs[i] = acc;
    }

    // ---- continuous stream: each warp does 18 rows (i = w + 2*ii), depth-4 pipeline ----
    #pragma unroll 1
    for (int ii = 0; ii < 18; ii++) {
        const int i = w + 2 * ii;
        const float4* np1 = (ii < 17) ? (p1 + 512) : p1;   // clamp: last iter reloads (discarded)
        const float4* np2 = (ii < 17) ? (p2 + 512) : p2;

        float aq0 = 0.f, an0 = 0.f, ax0 = 0.f, aq1 = 0.f, an1 = 0.f, ax1 = 0.f;
        { float4 a = A0, c = C0; A0 = __ldcs(p1 + 16); C0 = __ldcs(p2 + 16); dot3(aq0, an0, ax0, a, c); }
        { float4 a = A1, c = C1; A1 = __ldcs(p1 + 20); C1 = __ldcs(p2 + 20); dot3(aq0, an0, ax0, a, c); }
        { float4 a = A2, c = C2; A2 = __ldcs(p1 + 24); C2 = __ldcs(p2 + 24); dot3(aq0, an0, ax0, a, c); }
        { float4 a = A3, c = C3; A3 = __ldcs(p1 + 28); C3 = __ldcs(p2 + 28); dot3(aq0, an0, ax0, a, c); }
        { float4 a = A0, c = C0; A0 = __ldcs(np1 +  0); C0 = __ldcs(np2 +  0); dot3(aq1, an1, ax1, a, c); }
        { float4 a = A1, c = C1; A1 = __ldcs(np1 +  4); C1 = __ldcs(np2 +  4); dot3(aq1, an1, ax1, a, c); }
        { float4 a = A2, c = C2; A2 = __ldcs(np1 +  8); C2 = __ldcs(np2 +  8); dot3(aq1, an1, ax1, a, c); }
        { float4 a = A3, c = C3; A3 = __ldcs(np1 + 12); C3 = __ldcs(np2 + 12); dot3(aq1, an1, ax1, a, c); }

        #pragma unroll
        for (int m = 1; m < 4; m <<= 1) {
            aq0 += __shfl_xor_sync(0xffffffffu, aq0, m);
            an0 += __shfl_xor_sync(0xffffffffu, an0, m);
            ax0 += __shfl_xor_sync(0xffffffffu, ax0, m);
            aq1 += __shfl_xor_sync(0xffffffffu, aq1, m);
            an1 += __shfl_xor_sync(0xffffffffu, an1, m);
            ax1 += __shfl_xor_sync(0xffffffffu, ax1, m);
        }
        if (c4 == 0) {
            sv[i * SIMD + 2 * g]     = ax0 / ((sqrtf(aq0) + 1e-8f) * (sqrtf(an0) + 1e-8f));
            sv[i * SIMD + 2 * g + 1] = ax1 / ((sqrtf(aq1) + 1e-8f) * (sqrtf(an1) + 1e-8f));
        }
        p1 = np1; p2 = np2;
    }
    __syncthreads();

    // ---- fused tail: out = b2 + sum_{i,hh} w2s[hh]*tanh(b1[hh] + sum_d sv[i,d]*W1f[d,hh]) ----
    float part = 0.f;
    #pragma unroll
    for (int qq = 0; qq < 18; qq++) {
        const int p = tid + qq * 64;
        const int i = p >> 5, hh = p & 31;
        float acc = b1s[hh];
        #pragma unroll
        for (int d = 0; d < SIMD; d++)
            acc = fmaf(sv[i * SIMD + d], W1fs[d * HIDD + hh], acc);
        part = fmaf(w2ss[hh], tanhf(acc), part);
    }
    #pragma unroll
    for (int m = 1; m < 32; m <<= 1)
        part += __shfl_xor_sync(0xffffffffu, part, m);
    if (lane == 0) red[w] = part;
    __syncthreads();
    if (tid == 0)
        out[b] = b2sh + red[0] + red[1];
}

extern "C" void kernel_launch(void* const* d_in, const int* in_sizes, int n_in,
                              void* d_out, int out_size) {
    const int Bn = in_sizes[0] / (NREG * EMBD);
    simgsmn_main<<<Bn, 64>>>(
        (const float*)d_in[0], (const float*)d_in[1], (const float*)d_in[4],
        (const float*)d_in[5], (const float*)d_in[6], (const float*)d_in[7],
        (const float*)d_in[8], (const float*)d_in[9], (const float*)d_in[10],
        (float*)d_out);
}

// round 9
// speedup vs baseline: 1.2156x; 1.2156x over previous
#include <cuda_runtime.h>
#include <math.h>

#define NREG 36
#define EMBD 1024
#define SIMD 16
#define HIDD 32
#define NKER 8

__device__ __forceinline__ void dot3(float& q, float& n, float& x, const float4 a, const float4 c) {
    q = fmaf(a.x, a.x, q); q = fmaf(a.y, a.y, q); q = fmaf(a.z, a.z, q); q = fmaf(a.w, a.w, q);
    n = fmaf(c.x, c.x, n); n = fmaf(c.y, c.y, n); n = fmaf(c.z, c.z, n); n = fmaf(c.w, c.w, n);
    x = fmaf(a.x, c.x, x); x = fmaf(a.y, c.y, x); x = fmaf(a.z, c.z, x); x = fmaf(a.w, c.w, x);
}

// R5 shape exactly: 128 threads, grid = B, 9 CTAs/SM. Only change: constants
// folded in-kernel (behind the prologue loads) instead of a separate prep kernel.
__global__ void __launch_bounds__(128, 9)
simgsmn_main(const float* __restrict__ inp1, const float* __restrict__ inp2,
             const float* __restrict__ gcn_w, const float* __restrict__ out1_v,
             const float* __restrict__ out1_g, const float* __restrict__ out1_b,
             const float* __restrict__ out2_v, const float* __restrict__ out2_g,
             const float* __restrict__ out2_b, float* __restrict__ out)
{
    __shared__ float sv[NREG * SIMD];
    __shared__ float W1fs[SIMD * HIDD];
    __shared__ float gs[SIMD * HIDD];     // temp: sum_k gcn_w
    __shared__ float w1t[HIDD * HIDD];    // temp: weight-normed out1
    __shared__ float w2ss[HIDD];
    __shared__ float b1s[HIDD];
    __shared__ float red[4];
    __shared__ float b2sh;

    const int tid  = threadIdx.x;
    const int w    = tid >> 5;
    const int lane = tid & 31;
    const int g    = lane >> 2;     // group owns sim blocks {2g, 2g+1}
    const int c4   = lane & 3;
    const int b    = blockIdx.x;

    // ---- prologue loads FIRST: 16 LDG.128 in flight while constants fold ----
    const float4* p1 = reinterpret_cast<const float4*>(inp1)
                     + (size_t)b * (NREG * EMBD / 4) + w * 256 + g * 32 + c4;
    const float4* p2 = reinterpret_cast<const float4*>(inp2)
                     + (size_t)b * (NREG * EMBD / 4) + w * 256 + g * 32 + c4;

    float4 A0 = __ldcs(p1 +  0), C0 = __ldcs(p2 +  0);
    float4 A1 = __ldcs(p1 +  4), C1 = __ldcs(p2 +  4);
    float4 A2 = __ldcs(p1 +  8), C2 = __ldcs(p2 +  8);
    float4 A3 = __ldcs(p1 + 12), C3 = __ldcs(p2 + 12);

    // ---- per-CTA constant folding (L2-hot after the first CTAs) ----
    for (int i = tid; i < SIMD * HIDD; i += 128) {
        float a = 0.f;
        #pragma unroll
        for (int k = 0; k < NKER; k++) a += gcn_w[k * SIMD * HIDD + i];
        gs[i] = a;
    }
    if (tid < HIDD) {
        float ss = 0.f;
        #pragma unroll
        for (int h = 0; h < HIDD; h++) { float v = out1_v[tid * HIDD + h]; ss += v * v; }
        const float sc = out1_g[tid] / (sqrtf(ss) + 1e-12f);
        #pragma unroll
        for (int h = 0; h < HIDD; h++) w1t[tid * HIDD + h] = out1_v[tid * HIDD + h] * sc;
        b1s[tid] = out1_b[tid];
    }
    if (tid == 32) {
        float ss = 0.f;
        #pragma unroll
        for (int h = 0; h < HIDD; h++) { float v = out2_v[h]; ss += v * v; }
        const float sc = out2_g[0] / (sqrtf(ss) + 1e-12f);
        #pragma unroll
        for (int h = 0; h < HIDD; h++) w2ss[h] = out2_v[h] * sc * (1.0f / 36.0f);
        b2sh = out2_b[0];
    }
    __syncthreads();
    for (int i = tid; i < SIMD * HIDD; i += 128) {
        const int d = i >> 5, hh = i & 31;
        float acc = 0.f;
        #pragma unroll
        for (int h = 0; h < HIDD; h++)
            acc = fmaf(gs[d * HIDD + h], w1t[hh * HIDD + h], acc);
        W1fs[i] = acc;
    }

    // ---- R5 streaming core: depth-4 rotating pipeline, continuous across rows ----
    for (int ii = 0; ii < 9; ii++) {
        const int i = w + ii * 4;
        const float4* np1 = (ii < 8) ? (p1 + 1024) : p1;   // clamp: last iter reloads (discarded)
        const float4* np2 = (ii < 8) ? (p2 + 1024) : p2;
        float aq0 = 0.f, an0 = 0.f, ax0 = 0.f, aq1 = 0.f, an1 = 0.f, ax1 = 0.f;

        { float4 a = A0, c = C0; A0 = __ldcs(p1 + 16); C0 = __ldcs(p2 + 16); dot3(aq0, an0, ax0, a, c); }
        { float4 a = A1, c = C1; A1 = __ldcs(p1 + 20); C1 = __ldcs(p2 + 20); dot3(aq0, an0, ax0, a, c); }
        { float4 a = A2, c = C2; A2 = __ldcs(p1 + 24); C2 = __ldcs(p2 + 24); dot3(aq0, an0, ax0, a, c); }
        { float4 a = A3, c = C3; A3 = __ldcs(p1 + 28); C3 = __ldcs(p2 + 28); dot3(aq0, an0, ax0, a, c); }
        { float4 a = A0, c = C0; A0 = __ldcs(np1 +  0); C0 = __ldcs(np2 +  0); dot3(aq1, an1, ax1, a, c); }
        { float4 a = A1, c = C1; A1 = __ldcs(np1 +  4); C1 = __ldcs(np2 +  4); dot3(aq1, an1, ax1, a, c); }
        { float4 a = A2, c = C2; A2 = __ldcs(np1 +  8); C2 = __ldcs(np2 +  8); dot3(aq1, an1, ax1, a, c); }
        { float4 a = A3, c = C3; A3 = __ldcs(np1 + 12); C3 = __ldcs(np2 + 12); dot3(aq1, an1, ax1, a, c); }

        #pragma unroll
        for (int m = 1; m < 4; m <<= 1) {
            aq0 += __shfl_xor_sync(0xffffffffu, aq0, m);
            an0 += __shfl_xor_sync(0xffffffffu, an0, m);
            ax0 += __shfl_xor_sync(0xffffffffu, ax0, m);
            aq1 += __shfl_xor_sync(0xffffffffu, aq1, m);
            an1 += __shfl_xor_sync(0xffffffffu, an1, m);
            ax1 += __shfl_xor_sync(0xffffffffu, ax1, m);
        }
        if (c4 == 0) {
            sv[i * SIMD + 2 * g]     = ax0 / ((sqrtf(aq0) + 1e-8f) * (sqrtf(an0) + 1e-8f));
            sv[i * SIMD + 2 * g + 1] = ax1 / ((sqrtf(aq1) + 1e-8f) * (sqrtf(an1) + 1e-8f));
        }
        p1 = np1; p2 = np2;
    }
    __syncthreads();

    // ---- fused tail: out = b2 + sum_{i,hh} w2s[hh]*tanh(b1[hh] + sum_d sv[i,d]*W1f[d,hh]) ----
    float part = 0.f;
    #pragma unroll
    for (int qq = 0; qq < 9; qq++) {
        const int p = tid + qq * 128;
        const int i = p >> 5, hh = p & 31;
        float acc = b1s[hh];
        #pragma unroll
        for (int d = 0; d < SIMD; d++)
            acc = fmaf(sv[i * SIMD + d], W1fs[d * HIDD + hh], acc);
        part = fmaf(w2ss[hh], tanhf(acc), part);
    }
    #pragma unroll
    for (int m = 1; m < 32; m <<= 1)
        part += __shfl_xor_sync(0xffffffffu, part, m);
    if (lane == 0) red[w] = part;
    __syncthreads();
    if (tid == 0)
        out[b] = b2sh + red[0] + red[1] + red[2] + red[3];
}

extern "C" void kernel_launch(void* const* d_in, const int* in_sizes, int n_in,
                              void* d_out, int out_size) {
    const int Bn = in_sizes[0] / (NREG * EMBD);
    simgsmn_main<<<Bn, 128>>>(
        (const float*)d_in[0], (const float*)d_in[1], (const float*)d_in[4],
        (const float*)d_in[5], (const float*)d_in[6], (const float*)d_in[7],
        (const float*)d_in[8], (const float*)d_in[9], (const float*)d_in[10],
        (float*)d_out);
}

// round 10
// speedup vs baseline: 1.4987x; 1.2329x over previous
#include <cuda_runtime.h>
#include <math.h>

#define NREG 36
#define EMBD 1024
#define SIMD 16
#define HIDD 32
#define NKER 8

// Precomputed folded constants (prep_kernel -> main kernel)
__device__ float g_W1f[SIMD * HIDD];  // gsum · w1n^T folded: [d][hh]
__device__ float g_w2s[HIDD];         // weight-normed out2 row / 36
__device__ float g_b1[HIDD];
__device__ float g_b2;

__global__ void prep_kernel(const float* __restrict__ gcn_w,
                            const float* __restrict__ out1_v, const float* __restrict__ out1_g,
                            const float* __restrict__ out1_b, const float* __restrict__ out2_v,
                            const float* __restrict__ out2_g, const float* __restrict__ out2_b)
{
    __shared__ float gs[SIMD * HIDD];
    __shared__ float w1[HIDD * HIDD];
    const int tid = threadIdx.x;  // 512
    {
        float a = 0.f;
        #pragma unroll
        for (int k = 0; k < NKER; k++) a += gcn_w[k * SIMD * HIDD + tid];
        gs[tid] = a;
    }
    if (tid < HIDD) {
        float ss = 0.f;
        #pragma unroll
        for (int h = 0; h < HIDD; h++) { float v = out1_v[tid * HIDD + h]; ss += v * v; }
        const float sc = out1_g[tid] / (sqrtf(ss) + 1e-12f);
        #pragma unroll
        for (int h = 0; h < HIDD; h++) w1[tid * HIDD + h] = out1_v[tid * HIDD + h] * sc;
        g_b1[tid] = out1_b[tid];
    }
    if (tid == 32) {
        float ss = 0.f;
        #pragma unroll
        for (int h = 0; h < HIDD; h++) { float v = out2_v[h]; ss += v * v; }
        const float sc = out2_g[0] / (sqrtf(ss) + 1e-12f);
        #pragma unroll
        for (int h = 0; h < HIDD; h++) g_w2s[h] = out2_v[h] * sc * (1.0f / 36.0f);
        g_b2 = out2_b[0];
    }
    __syncthreads();
    {
        const int d = tid >> 5, hh = tid & 31;
        float acc = 0.f;
        #pragma unroll
        for (int h = 0; h < HIDD; h++)
            acc = fmaf(gs[d * HIDD + h], w1[hh * HIDD + h], acc);
        g_W1f[d * HIDD + hh] = acc;
    }
}

__device__ __forceinline__ void dot3(float& q, float& n, float& x, const float4 a, const float4 c) {
    q = fmaf(a.x, a.x, q); q = fmaf(a.y, a.y, q); q = fmaf(a.z, a.z, q); q = fmaf(a.w, a.w, q);
    n = fmaf(c.x, c.x, n); n = fmaf(c.y, c.y, n); n = fmaf(c.z, c.z, n); n = fmaf(c.w, c.w, n);
    x = fmaf(a.x, c.x, x); x = fmaf(a.y, c.y, x); x = fmaf(a.z, c.z, x); x = fmaf(a.w, c.w, x);
}

// Depth-8 rotating pipeline: entire next row (16 LDG.128) in flight while the
// current row is consumed. Slot-reuse period = one full row -> 9 exposed
// latency rounds per CTA instead of 18.
__global__ void __launch_bounds__(128, 6)
simgsmn_main(const float* __restrict__ inp1, const float* __restrict__ inp2,
             float* __restrict__ out)
{
    __shared__ float sv[NREG * SIMD];
    __shared__ float W1fs[SIMD * HIDD];
    __shared__ float w2ss[HIDD];
    __shared__ float b1s[HIDD];
    __shared__ float red[4];
    const int tid  = threadIdx.x;
    const int w    = tid >> 5;
    const int lane = tid & 31;
    const int g    = lane >> 2;     // group owns sim blocks {2g, 2g+1}
    const int c4   = lane & 3;
    const int b    = blockIdx.x;

    #pragma unroll
    for (int r = 0; r < 4; r++) W1fs[tid + r * 128] = g_W1f[tid + r * 128];
    if (tid < HIDD) { w2ss[tid] = g_w2s[tid]; b1s[tid] = g_b1[tid]; }

    const float4* p1 = reinterpret_cast<const float4*>(inp1)
                     + (size_t)b * (NREG * EMBD / 4) + w * 256 + g * 32 + c4;
    const float4* p2 = reinterpret_cast<const float4*>(inp2)
                     + (size_t)b * (NREG * EMBD / 4) + w * 256 + g * 32 + c4;

    // prologue: fill all 8 slot-pairs (entire first row in flight)
    float4 A0 = __ldcs(p1 +  0), C0 = __ldcs(p2 +  0);
    float4 A1 = __ldcs(p1 +  4), C1 = __ldcs(p2 +  4);
    float4 A2 = __ldcs(p1 +  8), C2 = __ldcs(p2 +  8);
    float4 A3 = __ldcs(p1 + 12), C3 = __ldcs(p2 + 12);
    float4 A4 = __ldcs(p1 + 16), C4 = __ldcs(p2 + 16);
    float4 A5 = __ldcs(p1 + 20), C5 = __ldcs(p2 + 20);
    float4 A6 = __ldcs(p1 + 24), C6 = __ldcs(p2 + 24);
    float4 A7 = __ldcs(p1 + 28), C7 = __ldcs(p2 + 28);

    #pragma unroll 1
    for (int ii = 0; ii < 9; ii++) {
        const int i   = w + ii * 4;
        const int adv = (ii < 8) ? 1024 : 0;   // clamp: last iter reloads current row (discarded)
        float aq0 = 0.f, an0 = 0.f, ax0 = 0.f, aq1 = 0.f, an1 = 0.f, ax1 = 0.f;

        { float4 a = A0, c = C0; A0 = __ldcs(p1 + adv +  0); C0 = __ldcs(p2 + adv +  0); dot3(aq0, an0, ax0, a, c); }
        { float4 a = A1, c = C1; A1 = __ldcs(p1 + adv +  4); C1 = __ldcs(p2 + adv +  4); dot3(aq0, an0, ax0, a, c); }
        { float4 a = A2, c = C2; A2 = __ldcs(p1 + adv +  8); C2 = __ldcs(p2 + adv +  8); dot3(aq0, an0, ax0, a, c); }
        { float4 a = A3, c = C3; A3 = __ldcs(p1 + adv + 12); C3 = __ldcs(p2 + adv + 12); dot3(aq0, an0, ax0, a, c); }
        { float4 a = A4, c = C4; A4 = __ldcs(p1 + adv + 16); C4 = __ldcs(p2 + adv + 16); dot3(aq1, an1, ax1, a, c); }
        { float4 a = A5, c = C5; A5 = __ldcs(p1 + adv + 20); C5 = __ldcs(p2 + adv + 20); dot3(aq1, an1, ax1, a, c); }
        { float4 a = A6, c = C6; A6 = __ldcs(p1 + adv + 24); C6 = __ldcs(p2 + adv + 24); dot3(aq1, an1, ax1, a, c); }
        { float4 a = A7, c = C7; A7 = __ldcs(p1 + adv + 28); C7 = __ldcs(p2 + adv + 28); dot3(aq1, an1, ax1, a, c); }

        #pragma unroll
        for (int m = 1; m < 4; m <<= 1) {
            aq0 += __shfl_xor_sync(0xffffffffu, aq0, m);
            an0 += __shfl_xor_sync(0xffffffffu, an0, m);
            ax0 += __shfl_xor_sync(0xffffffffu, ax0, m);
            aq1 += __shfl_xor_sync(0xffffffffu, aq1, m);
            an1 += __shfl_xor_sync(0xffffffffu, an1, m);
            ax1 += __shfl_xor_sync(0xffffffffu, ax1, m);
        }
        if (c4 == 0) {
            sv[i * SIMD + 2 * g]     = ax0 / ((sqrtf(aq0) + 1e-8f) * (sqrtf(an0) + 1e-8f));
            sv[i * SIMD + 2 * g + 1] = ax1 / ((sqrtf(aq1) + 1e-8f) * (sqrtf(an1) + 1e-8f));
        }
        p1 += adv; p2 += adv;
    }
    __syncthreads();

    // ---- fused tail: out = b2 + sum_{i,hh} w2s[hh]*tanh(b1[hh] + sum_d sv[i,d]*W1f[d,hh]) ----
    float part = 0.f;
    #pragma unroll
    for (int qq = 0; qq < 9; qq++) {
        const int p = tid + qq * 128;
        const int i = p >> 5, hh = p & 31;
        float acc = b1s[hh];
        #pragma unroll
        for (int d = 0; d < SIMD; d++)
            acc = fmaf(sv[i * SIMD + d], W1fs[d * HIDD + hh], acc);
        part = fmaf(w2ss[hh], tanhf(acc), part);
    }
    #pragma unroll
    for (int m = 1; m < 32; m <<= 1)
        part += __shfl_xor_sync(0xffffffffu, part, m);
    if (lane == 0) red[w] = part;
    __syncthreads();
    if (tid == 0)
        out[b] = g_b2 + red[0] + red[1] + red[2] + red[3];
}

extern "C" void kernel_launch(void* const* d_in, const int* in_sizes, int n_in,
                              void* d_out, int out_size) {
    const int Bn = in_sizes[0] / (NREG * EMBD);
    prep_kernel<<<1, 512>>>((const float*)d_in[4], (const float*)d_in[5],
                            (const float*)d_in[6], (const float*)d_in[7],
                            (const float*)d_in[8], (const float*)d_in[9],
                            (const float*)d_in[10]);
    simgsmn_main<<<Bn, 128>>>((const float*)d_in[0], (const float*)d_in[1], (float*)d_out);
}